// round 6
// baseline (speedup 1.0000x reference)
#include <cuda_runtime.h>
#include <cuda_bf16.h>

// Problem constants (fixed by the reference)
#define BB      2
#define XX      200
#define YY      200
#define ZZ      16      // == HEIGHT, h = 1
#define CC      17
#define EMPTY_LABEL 16
#define CHOOSE  4000

#define TPB 256
#define COLS_PER_BLK 16                       // 16 cols x 16 z = 256 voxels/block
#define BLKS_PER_B (CHOOSE / COLS_PER_BLK)    // 250
#define GRID2 (BB * BLKS_PER_B)               // 500
#define GRID1 ((BB * CHOOSE + TPB - 1) / TPB) // 32

// Persistent device scratch (allocation-free).
// g_cnt / g_loss start zero (static init) and are re-zeroed by the last K2
// block every call, so each call/replay starts from zeros.
// g_ticket is a MONOTONIC epoch counter (never reset).
__device__ int                 g_cnt[BB * ZZ];
__device__ float               g_loss[BB];
__device__ unsigned long long  g_ticket;

// ---------------------------------------------------------------------------
// K1: per-(b,z) valid-label counts. 8000 columns, one thread each.
// Warps never straddle the batch boundary (4000 = 125 * 32).
__global__ void __launch_bounds__(TPB)
k1_counts(const int* __restrict__ labels, const int* __restrict__ sel) {
    __shared__ int s_cnt[BB * ZZ];
    const int tid = threadIdx.x;
    const int t = blockIdx.x * TPB + tid;
    if (tid < BB * ZZ) s_cnt[tid] = 0;
    __syncthreads();

    if (t < BB * CHOOSE) {
        const int b = t / CHOOSE;
        const int2 xy = __ldg((const int2*)sel + t);   // t = b*CHOOSE + i
        const int col = (b * XX + xy.x) * YY + xy.y;
        const int4* __restrict__ lp = (const int4*)(labels + (long long)col * ZZ);
        int4 l[4];
        #pragma unroll
        for (int q = 0; q < 4; q++) l[q] = __ldg(lp + q);

        const int lane = tid & 31;
        #pragma unroll
        for (int q = 0; q < 4; q++) {
            unsigned m0 = __ballot_sync(0xffffffffu, l[q].x != EMPTY_LABEL);
            unsigned m1 = __ballot_sync(0xffffffffu, l[q].y != EMPTY_LABEL);
            unsigned m2 = __ballot_sync(0xffffffffu, l[q].z != EMPTY_LABEL);
            unsigned m3 = __ballot_sync(0xffffffffu, l[q].w != EMPTY_LABEL);
            if (lane == 0) {
                atomicAdd(&s_cnt[b * ZZ + q * 4 + 0], __popc(m0));
                atomicAdd(&s_cnt[b * ZZ + q * 4 + 1], __popc(m1));
                atomicAdd(&s_cnt[b * ZZ + q * 4 + 2], __popc(m2));
                atomicAdd(&s_cnt[b * ZZ + q * 4 + 3], __popc(m3));
            }
        }
    }
    __syncthreads();
    if (tid < BB * ZZ && s_cnt[tid]) atomicAdd(&g_cnt[tid], s_cnt[tid]);
}

// ---------------------------------------------------------------------------
// K2: softmax + weighted smooth-L1 loss. No grid barrier: weights come from
// g_cnt (written by K1; kernel-boundary ordering guarantees visibility).
__global__ void __launch_bounds__(TPB)
k2_loss(const float* __restrict__ preds,
        const int*   __restrict__ labels,
        const int*   __restrict__ sel,
        float*       __restrict__ out) {
    const int bid = blockIdx.x;
    const int tid = threadIdx.x;
    const int b  = bid / BLKS_PER_B;
    const int cb = bid % BLKS_PER_B;

    __shared__ float s_pred[COLS_PER_BLK * ZZ * CC];   // 17408B
    __shared__ int   s_lab [COLS_PER_BLK * ZZ];
    __shared__ int   s_col [COLS_PER_BLK];
    __shared__ int   s_ci  [ZZ];
    __shared__ float s_w   [ZZ];

    // stage sel -> columns, and counts -> s_ci (L2 hit) in parallel
    if (tid < COLS_PER_BLK) {
        int2 xy = __ldg((const int2*)sel + b * CHOOSE + cb * COLS_PER_BLK + tid);
        s_col[tid] = (b * XX + xy.x) * YY + xy.y;
    } else if (tid < 2 * COLS_PER_BLK) {
        s_ci[tid - COLS_PER_BLK] = g_cnt[b * ZZ + (tid - COLS_PER_BLK)];
    }
    __syncthreads();

    // weights (16 threads) — overlaps with staging below in other warps
    if (tid < ZZ) {
        int maxc = 0;
        #pragma unroll
        for (int z2 = 0; z2 < ZZ; z2++) maxc = max(maxc, s_ci[z2]);
        float maxcf = fmaxf((float)maxc, 1.0f);
        int c = s_ci[tid];
        const float LOG_RATIO = -1.0986122886681098f;   // ln(1/3)
        s_w[tid] = (c > 0) ? 3.0f * __expf(((float)c / maxcf) * LOG_RATIO) : 0.0f;
    } else if (tid >= 64 && tid < 128) {
        // labels: 16 cols x 4 int4 (coalesced)
        int u = tid - 64;
        int lc = u >> 2, i4 = u & 3;
        ((int4*)s_lab)[lc * 4 + i4] =
            __ldg((const int4*)(labels + (long long)s_col[lc] * ZZ) + i4);
    }

    // preds: 16 cols x 68 float4 (coalesced)
    {
        const int w = tid >> 5, lane = tid & 31;
        #pragma unroll
        for (int cc = 0; cc < 2; cc++) {
            const int lc = w * 2 + cc;
            const float4* __restrict__ src =
                (const float4*)preds + (long long)s_col[lc] * 68;   // 272 floats
            float4* dst = (float4*)(s_pred + lc * (ZZ * CC));
            dst[lane]      = __ldg(src + lane);
            dst[lane + 32] = __ldg(src + lane + 32);
            if (lane < 4) dst[lane + 64] = __ldg(src + lane + 64);
        }
    }
    __syncthreads();

    // per-voxel loss
    const int lc = tid >> 4;
    const int z  = tid & 15;
    const int lab = s_lab[lc * ZZ + z];
    float val = 0.0f;
    if (lab != EMPTY_LABEL) {
        const float* __restrict__ p = s_pred + lc * (ZZ * CC) + z * CC;
        float s = 0.0f;
        #pragma unroll
        for (int c = 0; c < CC; c++) s += __expf(p[c]);   // conflict-free LDS
        const float plab = __fdividef(__expf(p[lab]), s);
        const float ll = __logf(plab + 0.001f);
        const float wl = s_w[z] * ll;
        const float ax = fabsf(wl);
        val = (ax < 1.0f) ? 0.5f * wl * wl : (ax - 0.5f);
    }

    // block reduce -> per-batch atomic
    #pragma unroll
    for (int off = 16; off > 0; off >>= 1)
        val += __shfl_down_sync(0xffffffffu, val, off);
    __shared__ float s_warp[TPB / 32];
    const int wid = tid >> 5, lid = tid & 31;
    if (lid == 0) s_warp[wid] = val;
    __syncthreads();
    if (wid == 0) {
        float v = (lid < TPB / 32) ? s_warp[lid] : 0.0f;
        #pragma unroll
        for (int off = 4; off > 0; off >>= 1)
            v += __shfl_down_sync(0xffffffffu, v, off);
        if (lid == 0) {
            atomicAdd(&g_loss[b], v);
            __threadfence();
        }
    }
    __syncthreads();

    // last block: finalize + reset accumulators
    __shared__ int s_last;
    if (tid == 0) {
        unsigned long long old = atomicAdd(&g_ticket, 1ULL);
        s_last = ((old % GRID2) == (GRID2 - 1)) ? 1 : 0;
    }
    __syncthreads();
    if (!s_last) return;

    if (tid == 0) {
        __threadfence();  // acquire all g_loss updates
        int n0 = 0, n1 = 0;
        #pragma unroll
        for (int z2 = 0; z2 < ZZ; z2++) { n0 += g_cnt[z2]; n1 += g_cnt[ZZ + z2]; }
        float r0 = g_loss[0] / fmaxf((float)n0, 1.0f);
        float r1 = g_loss[1] / fmaxf((float)n1, 1.0f);
        out[0] = 0.5f * (r0 + r1);
        // reset for next call (graph replay / re-validation)
        #pragma unroll
        for (int z2 = 0; z2 < BB * ZZ; z2++) g_cnt[z2] = 0;
        g_loss[0] = 0.0f;
        g_loss[1] = 0.0f;
    }
}

extern "C" void kernel_launch(void* const* d_in, const int* in_sizes, int n_in,
                              void* d_out, int out_size) {
    const float* preds  = nullptr;
    const int*   labels = nullptr;
    const int*   sel    = nullptr;
    for (int i = 0; i < n_in; i++) {
        if (in_sizes[i] == BB * XX * YY * ZZ * CC)      preds  = (const float*)d_in[i];
        else if (in_sizes[i] == BB * XX * YY * ZZ)      labels = (const int*)d_in[i];
        else if (in_sizes[i] == BB * CHOOSE * 2)        sel    = (const int*)d_in[i];
    }
    k1_counts<<<GRID1, TPB>>>(labels, sel);
    k2_loss<<<GRID2, TPB>>>(preds, labels, sel, (float*)d_out);
}

// round 7
// speedup vs baseline: 1.0312x; 1.0312x over previous
#include <cuda_runtime.h>
#include <cuda_bf16.h>

// Problem constants (fixed by the reference)
#define BB      2
#define XX      200
#define YY      200
#define ZZ      16      // == HEIGHT, h = 1
#define CC      17
#define EMPTY_LABEL 16
#define CHOOSE  4000

#define TPB 256
#define COLS_PER_BLK 16
#define BLKS_PER_B (CHOOSE / COLS_PER_BLK)    // 250
#define GRID2 (BB * BLKS_PER_B)               // 500
#define GRID1 ((BB * CHOOSE + TPB - 1) / TPB) // 32

// Persistent device scratch (allocation-free).
// g_cnt / g_loss start zero (static init) and are re-zeroed by the last K2
// block every call, so each call/replay starts from zeros.
// g_ticket is MONOTONIC (never reset).
__device__ int                 g_cnt[BB * ZZ];
__device__ float               g_loss[BB];
__device__ unsigned long long  g_ticket;

// ---------------------------------------------------------------------------
// K1: per-(b,z) valid-label counts. 8000 columns, one thread each.
__global__ void __launch_bounds__(TPB)
k1_counts(const int* __restrict__ labels, const int* __restrict__ sel) {
    __shared__ int s_cnt[BB * ZZ];
    const int tid = threadIdx.x;
    const int t = blockIdx.x * TPB + tid;
    if (tid < BB * ZZ) s_cnt[tid] = 0;
    __syncthreads();

    if (t < BB * CHOOSE) {
        const int b = t / CHOOSE;
        const int2 xy = __ldg((const int2*)sel + t);
        const int col = (b * XX + xy.x) * YY + xy.y;
        const int4* __restrict__ lp = (const int4*)(labels + (long long)col * ZZ);
        int4 l[4];
        #pragma unroll
        for (int q = 0; q < 4; q++) l[q] = __ldg(lp + q);

        const int lane = tid & 31;
        #pragma unroll
        for (int q = 0; q < 4; q++) {
            unsigned m0 = __ballot_sync(0xffffffffu, l[q].x != EMPTY_LABEL);
            unsigned m1 = __ballot_sync(0xffffffffu, l[q].y != EMPTY_LABEL);
            unsigned m2 = __ballot_sync(0xffffffffu, l[q].z != EMPTY_LABEL);
            unsigned m3 = __ballot_sync(0xffffffffu, l[q].w != EMPTY_LABEL);
            if (lane == 0) {
                atomicAdd(&s_cnt[b * ZZ + q * 4 + 0], __popc(m0));
                atomicAdd(&s_cnt[b * ZZ + q * 4 + 1], __popc(m1));
                atomicAdd(&s_cnt[b * ZZ + q * 4 + 2], __popc(m2));
                atomicAdd(&s_cnt[b * ZZ + q * 4 + 3], __popc(m3));
            }
        }
    }
    __syncthreads();
    if (tid < BB * ZZ && s_cnt[tid]) atomicAdd(&g_cnt[tid], s_cnt[tid]);
}

// ---------------------------------------------------------------------------
// K2: warp-autonomous. Warp w owns columns {2w, 2w+1} of its 16-col tile:
// stages them, computes weights in registers, does softmax+loss — with NO
// block-wide sync until the final 8-value combine.
__global__ void __launch_bounds__(TPB)
k2_loss(const float* __restrict__ preds,
        const int*   __restrict__ labels,
        const int*   __restrict__ sel,
        float*       __restrict__ out) {
    const int bid = blockIdx.x;
    const int tid = threadIdx.x;
    const int b  = bid / BLKS_PER_B;
    const int cb = bid % BLKS_PER_B;
    const int w    = tid >> 5;
    const int lane = tid & 31;

    __shared__ float s_pred[COLS_PER_BLK * ZZ * CC];   // 17408B
    __shared__ int   s_lab [COLS_PER_BLK * ZZ];
    __shared__ float s_wsum[TPB / 32];

    // ---- sel for this warp's 2 columns (lanes 0,1), broadcast -------------
    int colv = 0;
    if (lane < 2) {
        int2 xy = __ldg((const int2*)sel + b * CHOOSE + cb * COLS_PER_BLK + 2 * w + lane);
        colv = (b * XX + xy.x) * YY + xy.y;
    }
    const int colA = __shfl_sync(0xffffffffu, colv, 0);
    const int colB = __shfl_sync(0xffffffffu, colv, 1);

    // ---- fire pred loads (8.5 float4 per warp, all independent) -----------
    {
        const float4* __restrict__ srcA = (const float4*)preds + (long long)colA * 68;
        const float4* __restrict__ srcB = (const float4*)preds + (long long)colB * 68;
        float4* dstA = (float4*)(s_pred + (2 * w)     * (ZZ * CC));
        float4* dstB = (float4*)(s_pred + (2 * w + 1) * (ZZ * CC));
        dstA[lane]      = __ldg(srcA + lane);
        dstB[lane]      = __ldg(srcB + lane);
        dstA[lane + 32] = __ldg(srcA + lane + 32);
        dstB[lane + 32] = __ldg(srcB + lane + 32);
        if (lane < 4) {
            dstA[lane + 64] = __ldg(srcA + lane + 64);
            dstB[lane + 64] = __ldg(srcB + lane + 64);
        }
    }
    // ---- labels for both columns (lanes 0-7) -------------------------------
    if (lane < 8) {
        int c = (lane < 4) ? colA : colB;
        int q = lane & 3;
        ((int4*)s_lab)[(2 * w + (lane >> 2)) * 4 + q] =
            __ldg((const int4*)(labels + (long long)c * ZZ) + q);
    }

    // ---- weights in registers (overlaps the DRAM wait) ---------------------
    const int z = lane & 15;
    const int cz = g_cnt[b * ZZ + z];            // L2 hit (written by K1)
    int maxc = cz;
    #pragma unroll
    for (int o = 1; o < 16; o <<= 1)
        maxc = max(maxc, __shfl_xor_sync(0xffffffffu, maxc, o));
    const float maxcf = fmaxf((float)maxc, 1.0f);
    const float LOG_RATIO = -1.0986122886681098f;   // ln(1/3)
    const float wz = (cz > 0) ? 3.0f * __expf(((float)cz / maxcf) * LOG_RATIO) : 0.0f;

    __syncwarp();   // warp's own stores visible to itself

    // ---- softmax + smooth-L1: lane -> (col = 2w + (lane>>4), z = lane&15) --
    const int lcl = lane >> 4;
    const int lab = s_lab[(2 * w + lcl) * ZZ + z];
    float val = 0.0f;
    if (lab != EMPTY_LABEL) {
        const float* __restrict__ p = s_pred + (2 * w + lcl) * (ZZ * CC) + z * CC;
        float s = 0.0f;
        #pragma unroll
        for (int c = 0; c < CC; c++) s += __expf(p[c]);   // conflict-free LDS
        const float plab = __fdividef(__expf(p[lab]), s);
        const float ll = __logf(plab + 0.001f);
        const float wl = wz * ll;
        const float ax = fabsf(wl);
        val = (ax < 1.0f) ? 0.5f * wl * wl : (ax - 0.5f);
    }

    // ---- warp reduce -> smem; single block sync; one global atomic ---------
    #pragma unroll
    for (int off = 16; off > 0; off >>= 1)
        val += __shfl_down_sync(0xffffffffu, val, off);
    if (lane == 0) s_wsum[w] = val;
    __syncthreads();

    if (tid == 0) {
        float v = 0.0f;
        #pragma unroll
        for (int i = 0; i < TPB / 32; i++) v += s_wsum[i];
        atomicAdd(&g_loss[b], v);
        __threadfence();

        // ticket: last block finalizes + resets accumulators
        unsigned long long old = atomicAdd(&g_ticket, 1ULL);
        if ((old % GRID2) == (GRID2 - 1)) {
            __threadfence();  // acquire all g_loss updates
            int n0 = 0, n1 = 0;
            #pragma unroll
            for (int z2 = 0; z2 < ZZ; z2++) { n0 += g_cnt[z2]; n1 += g_cnt[ZZ + z2]; }
            float r0 = g_loss[0] / fmaxf((float)n0, 1.0f);
            float r1 = g_loss[1] / fmaxf((float)n1, 1.0f);
            out[0] = 0.5f * (r0 + r1);
            // reset for next call (graph replay / re-validation)
            #pragma unroll
            for (int z2 = 0; z2 < BB * ZZ; z2++) g_cnt[z2] = 0;
            g_loss[0] = 0.0f;
            g_loss[1] = 0.0f;
        }
    }
}

extern "C" void kernel_launch(void* const* d_in, const int* in_sizes, int n_in,
                              void* d_out, int out_size) {
    const float* preds  = nullptr;
    const int*   labels = nullptr;
    const int*   sel    = nullptr;
    for (int i = 0; i < n_in; i++) {
        if (in_sizes[i] == BB * XX * YY * ZZ * CC)      preds  = (const float*)d_in[i];
        else if (in_sizes[i] == BB * XX * YY * ZZ)      labels = (const int*)d_in[i];
        else if (in_sizes[i] == BB * CHOOSE * 2)        sel    = (const int*)d_in[i];
    }
    k1_counts<<<GRID1, TPB>>>(labels, sel);
    k2_loss<<<GRID2, TPB>>>(preds, labels, sel, (float*)d_out);
}

// round 8
// speedup vs baseline: 1.1028x; 1.0694x over previous
#include <cuda_runtime.h>
#include <cuda_bf16.h>

// Problem constants (fixed by the reference)
#define BB      2
#define XX      200
#define YY      200
#define ZZ      16      // == HEIGHT, h = 1
#define CC      17
#define EMPTY_LABEL 16
#define CHOOSE  4000

#define TPB 256
#define COLS_PER_BLK 16
#define BLKS_PER_B (CHOOSE / COLS_PER_BLK)    // 250
#define GRID2 (BB * BLKS_PER_B)               // 500
#define GRID1 ((BB * CHOOSE + TPB - 1) / TPB) // 32

// Persistent device scratch (allocation-free).
// g_cnt / g_loss start zero (static init) and are re-zeroed by the last K2
// block every call. g_ticket is MONOTONIC (never reset).
__device__ int                 g_cnt[BB * ZZ];
__device__ float               g_loss[BB];
__device__ unsigned long long  g_ticket;

__device__ __forceinline__ void cp16(unsigned smem_addr, const void* gptr) {
    asm volatile("cp.async.cg.shared.global [%0], [%1], 16;"
                 :: "r"(smem_addr), "l"(gptr));
}

// ---------------------------------------------------------------------------
// K1: per-(b,z) valid-label counts. 8000 columns, one thread each.
__global__ void __launch_bounds__(TPB)
k1_counts(const int* __restrict__ labels, const int* __restrict__ sel) {
    __shared__ int s_cnt[BB * ZZ];
    const int tid = threadIdx.x;
    const int t = blockIdx.x * TPB + tid;
    if (tid < BB * ZZ) s_cnt[tid] = 0;
    __syncthreads();

    if (t < BB * CHOOSE) {
        const int b = t / CHOOSE;
        const int2 xy = __ldg((const int2*)sel + t);
        const int col = (b * XX + xy.x) * YY + xy.y;
        const int4* __restrict__ lp = (const int4*)(labels + (long long)col * ZZ);
        int4 l[4];
        #pragma unroll
        for (int q = 0; q < 4; q++) l[q] = __ldg(lp + q);

        const int lane = tid & 31;
        #pragma unroll
        for (int q = 0; q < 4; q++) {
            unsigned m0 = __ballot_sync(0xffffffffu, l[q].x != EMPTY_LABEL);
            unsigned m1 = __ballot_sync(0xffffffffu, l[q].y != EMPTY_LABEL);
            unsigned m2 = __ballot_sync(0xffffffffu, l[q].z != EMPTY_LABEL);
            unsigned m3 = __ballot_sync(0xffffffffu, l[q].w != EMPTY_LABEL);
            if (lane == 0) {
                atomicAdd(&s_cnt[b * ZZ + q * 4 + 0], __popc(m0));
                atomicAdd(&s_cnt[b * ZZ + q * 4 + 1], __popc(m1));
                atomicAdd(&s_cnt[b * ZZ + q * 4 + 2], __popc(m2));
                atomicAdd(&s_cnt[b * ZZ + q * 4 + 3], __popc(m3));
            }
        }
    }
    __syncthreads();
    if (tid < BB * ZZ && s_cnt[tid]) atomicAdd(&g_cnt[tid], s_cnt[tid]);
}

// ---------------------------------------------------------------------------
// K2: warp-autonomous, register-free staging via cp.async. Warp w owns
// columns {2w, 2w+1}: fires all 19 async 16B copies at once (MLP=19 per warp,
// independent of regcount), computes weights while they fly, then softmax.
__global__ void __launch_bounds__(TPB)
k2_loss(const float* __restrict__ preds,
        const int*   __restrict__ labels,
        const int*   __restrict__ sel,
        float*       __restrict__ out) {
    const int bid = blockIdx.x;
    const int tid = threadIdx.x;
    const int b  = bid / BLKS_PER_B;
    const int cb = bid % BLKS_PER_B;
    const int w    = tid >> 5;
    const int lane = tid & 31;

    __shared__ float s_pred[COLS_PER_BLK * ZZ * CC];   // 17408B
    __shared__ int   s_lab [COLS_PER_BLK * ZZ];        // 1KB
    __shared__ float s_wsum[TPB / 32];

    // ---- sel for this warp's 2 columns (lanes 0,1), broadcast --------------
    int colv = 0;
    if (lane < 2) {
        int2 xy = __ldg((const int2*)sel + b * CHOOSE + cb * COLS_PER_BLK + 2 * w + lane);
        colv = (b * XX + xy.x) * YY + xy.y;
    }
    const int colA = __shfl_sync(0xffffffffu, colv, 0);
    const int colB = __shfl_sync(0xffffffffu, colv, 1);

    // ---- fire ALL staging as cp.async (no register buffering) --------------
    {
        const float4* __restrict__ srcA = (const float4*)preds + (long long)colA * 68;
        const float4* __restrict__ srcB = (const float4*)preds + (long long)colB * 68;
        unsigned dstA = (unsigned)__cvta_generic_to_shared(s_pred + (2 * w)     * (ZZ * CC));
        unsigned dstB = (unsigned)__cvta_generic_to_shared(s_pred + (2 * w + 1) * (ZZ * CC));
        cp16(dstA + lane * 16,        srcA + lane);
        cp16(dstB + lane * 16,        srcB + lane);
        cp16(dstA + (lane + 32) * 16, srcA + lane + 32);
        cp16(dstB + (lane + 32) * 16, srcB + lane + 32);
        if (lane < 4) {
            cp16(dstA + (lane + 64) * 16, srcA + lane + 64);
            cp16(dstB + (lane + 64) * 16, srcB + lane + 64);
        }
        // labels: 2 cols x 64B = 8 x 16B chunks (lanes 0-7)
        if (lane < 8) {
            int c = (lane < 4) ? colA : colB;
            unsigned dl = (unsigned)__cvta_generic_to_shared(
                              s_lab + (2 * w + (lane >> 2)) * ZZ) + (lane & 3) * 16;
            cp16(dl, (const int4*)(labels + (long long)c * ZZ) + (lane & 3));
        }
        asm volatile("cp.async.commit_group;");
    }

    // ---- weights in registers (overlaps the async fetch) -------------------
    const int z = lane & 15;
    const int cz = g_cnt[b * ZZ + z];            // L2 hit (written by K1)
    int maxc = cz;
    #pragma unroll
    for (int o = 1; o < 16; o <<= 1)
        maxc = max(maxc, __shfl_xor_sync(0xffffffffu, maxc, o));
    const float maxcf = fmaxf((float)maxc, 1.0f);
    const float LOG_RATIO = -1.0986122886681098f;   // ln(1/3)
    const float wz = (cz > 0) ? 3.0f * __expf(((float)cz / maxcf) * LOG_RATIO) : 0.0f;

    // ---- wait for this warp's copies; consume from smem --------------------
    asm volatile("cp.async.wait_group 0;");
    __syncwarp();

    const int lcl = lane >> 4;
    const int lab = s_lab[(2 * w + lcl) * ZZ + z];
    float val = 0.0f;
    if (lab != EMPTY_LABEL) {
        const float* __restrict__ p = s_pred + (2 * w + lcl) * (ZZ * CC) + z * CC;
        float s = 0.0f;
        #pragma unroll
        for (int c = 0; c < CC; c++) s += __expf(p[c]);   // conflict-free LDS
        const float plab = __fdividef(__expf(p[lab]), s);
        const float ll = __logf(plab + 0.001f);
        const float wl = wz * ll;
        const float ax = fabsf(wl);
        val = (ax < 1.0f) ? 0.5f * wl * wl : (ax - 0.5f);
    }

    // ---- warp reduce -> smem; single block sync; one global atomic ---------
    #pragma unroll
    for (int off = 16; off > 0; off >>= 1)
        val += __shfl_down_sync(0xffffffffu, val, off);
    if (lane == 0) s_wsum[w] = val;
    __syncthreads();

    if (tid == 0) {
        float v = 0.0f;
        #pragma unroll
        for (int i = 0; i < TPB / 32; i++) v += s_wsum[i];
        atomicAdd(&g_loss[b], v);
        __threadfence();

        // ticket: last block finalizes + resets accumulators
        unsigned long long old = atomicAdd(&g_ticket, 1ULL);
        if ((old % GRID2) == (GRID2 - 1)) {
            __threadfence();  // acquire all g_loss updates
            int n0 = 0, n1 = 0;
            #pragma unroll
            for (int z2 = 0; z2 < ZZ; z2++) { n0 += g_cnt[z2]; n1 += g_cnt[ZZ + z2]; }
            float r0 = g_loss[0] / fmaxf((float)n0, 1.0f);
            float r1 = g_loss[1] / fmaxf((float)n1, 1.0f);
            out[0] = 0.5f * (r0 + r1);
            // reset for next call (graph replay / re-validation)
            #pragma unroll
            for (int z2 = 0; z2 < BB * ZZ; z2++) g_cnt[z2] = 0;
            g_loss[0] = 0.0f;
            g_loss[1] = 0.0f;
        }
    }
}

extern "C" void kernel_launch(void* const* d_in, const int* in_sizes, int n_in,
                              void* d_out, int out_size) {
    const float* preds  = nullptr;
    const int*   labels = nullptr;
    const int*   sel    = nullptr;
    for (int i = 0; i < n_in; i++) {
        if (in_sizes[i] == BB * XX * YY * ZZ * CC)      preds  = (const float*)d_in[i];
        else if (in_sizes[i] == BB * XX * YY * ZZ)      labels = (const int*)d_in[i];
        else if (in_sizes[i] == BB * CHOOSE * 2)        sel    = (const int*)d_in[i];
    }
    k1_counts<<<GRID1, TPB>>>(labels, sel);
    k2_loss<<<GRID2, TPB>>>(preds, labels, sel, (float*)d_out);
}